// round 5
// baseline (speedup 1.0000x reference)
#include <cuda_runtime.h>
#include <cuda_bf16.h>

// Dconv: x[8,32,224,224] f32, W[1,8,3,3], Bv[8]
// out[b, f*32+c, ho, wo] = sum_{i,j} x[b,c,ho+i,wo+j]*W[0,f,i,j] + Bv[f]
// out shape [8, 256, 222, 222] f32.
//
// HBM-store-bound kernel (~404 MB output). Uses fma.rn.f32x2 (packed 2-wide
// f32 FMA) so scalar-FMA issue doesn't co-dominate with the HBM floor.

#define KFMA2(d, a, b, c) \
    asm("fma.rn.f32x2 %0, %1, %2, %3;" : "=l"(d) : "l"(a), "l"(b), "l"(c))
#define KPACK2(d, lo, hi) \
    asm("mov.b64 %0, {%1, %2};" : "=l"(d) \
        : "r"(__float_as_uint(lo)), "r"(__float_as_uint(hi)))

static constexpr int Hc   = 224;
static constexpr int Ho   = 222;
static constexpr int C    = 32;
static constexpr int NF   = 8;
static constexpr int IN_PLANE  = Hc * Hc;       // 50176
static constexpr int OUT_PLANE = Ho * Ho;       // 49284

__global__ __launch_bounds__(256)
void dconv_f32x2_kernel(const float* __restrict__ x,
                        const float* __restrict__ W,
                        const float* __restrict__ Bv,
                        float* __restrict__ out)
{
    __shared__ unsigned long long s_w[NF * 9];  // {w,w} packed f32x2
    __shared__ unsigned long long s_b[NF];      // {bv,bv}

    const int tid = threadIdx.y * 32 + threadIdx.x;
    if (tid < NF * 9) {
        float w = W[tid];                       // W[1,8,3,3] contiguous: f*9 + i*3 + j
        unsigned long long pw;
        KPACK2(pw, w, w);
        s_w[tid] = pw;
    } else if (tid < NF * 9 + NF) {
        float bv = Bv[tid - NF * 9];
        unsigned long long pb;
        KPACK2(pb, bv, bv);
        s_b[tid - NF * 9] = pb;
    }
    __syncthreads();

    const int p   = blockIdx.z;                          // b*32 + c
    const int wo0 = (blockIdx.x * 32 + threadIdx.x) * 4; // 4 output cols / thread
    const int ho  = blockIdx.y * 8 + threadIdx.y;
    if (ho >= Ho || wo0 >= Ho) return;

    // ---- load 3x6 input window into registers (vectorized, 16B aligned) ----
    const float* xp = x + (size_t)p * IN_PLANE + (size_t)ho * Hc + wo0;
    float in[3][6];
    if (wo0 <= Ho - 4) {                 // wo0 <= 218 -> cols wo0..wo0+5 <= 223, in-bounds
        #pragma unroll
        for (int r = 0; r < 3; r++) {
            const float* rp = xp + r * Hc;
            float4 a  = *reinterpret_cast<const float4*>(rp);
            float2 b2 = *reinterpret_cast<const float2*>(rp + 4);
            in[r][0] = a.x;  in[r][1] = a.y;  in[r][2] = a.z;
            in[r][3] = a.w;  in[r][4] = b2.x; in[r][5] = b2.y;
        }
    } else {                             // wo0 == 220: cols 224,225 OOB -> guard
        #pragma unroll
        for (int r = 0; r < 3; r++) {
            const float* rp = xp + r * Hc;
            #pragma unroll
            for (int j = 0; j < 6; j++)
                in[r][j] = (wo0 + j < Hc) ? rp[j] : 0.0f;
        }
    }

    // ---- pack pixel-pairs for f32x2: pair0 = (wo0,wo0+1), pair1 = (wo0+2,wo0+3) ----
    unsigned long long pk0[9], pk1[9];
    #pragma unroll
    for (int r = 0; r < 3; r++) {
        #pragma unroll
        for (int j = 0; j < 3; j++) {
            KPACK2(pk0[r * 3 + j], in[r][j],     in[r][j + 1]);
            KPACK2(pk1[r * 3 + j], in[r][j + 2], in[r][j + 3]);
        }
    }

    const bool full = (wo0 <= Ho - 4);   // pair1 (cols wo0+2,wo0+3) in range?
    const int  b    = p >> 5;
    const int  c    = p & 31;
    float* obase = out + ((size_t)(b * (NF * C) + c) * Ho + ho) * Ho + wo0;

    #pragma unroll
    for (int f = 0; f < NF; f++) {
        unsigned long long acc0 = s_b[f];
        unsigned long long acc1 = s_b[f];
        #pragma unroll
        for (int t = 0; t < 9; t++) {
            unsigned long long w2 = s_w[f * 9 + t];
            KFMA2(acc0, pk0[t], w2, acc0);
            KFMA2(acc1, pk1[t], w2, acc1);
        }
        float* op = obase + (size_t)f * (C * OUT_PLANE);
        *reinterpret_cast<float2*>(op) = *reinterpret_cast<float2*>(&acc0);
        if (full)
            *reinterpret_cast<float2*>(op + 2) = *reinterpret_cast<float2*>(&acc1);
    }
}

extern "C" void kernel_launch(void* const* d_in, const int* in_sizes, int n_in,
                              void* d_out, int out_size)
{
    const float* x  = (const float*)d_in[0];
    const float* W  = (const float*)d_in[1];
    const float* Bv = (const float*)d_in[2];
    float* out = (float*)d_out;

    dim3 block(32, 8);                       // 256 threads
    dim3 grid(2, 28, 8 * 32);                // ceil(222/128), ceil(222/8), B*C
    dconv_f32x2_kernel<<<grid, block>>>(x, W, Bv, out);
}